// round 17
// baseline (speedup 1.0000x reference)
#include <cuda_runtime.h>
#include <cstdint>

// Problem constants
#define N_HEAD   16
#define C_EMBD   1024
#define HEAD_D   64
#define CHUNK    64
#define BATCH    4
#define SEQ      4096
#define M_TOK    (BATCH * SEQ)          // 16384 tokens
#define F_QKV    (3 * C_EMBD)           // 3072

// Scratch buffers (no cudaMalloc allowed anywhere)
__device__ __align__(16) float    g_qkv[M_TOK * F_QKV];   // fp32 qkv   ~201 MB
__device__ __align__(16) uint32_t g_xa[M_TOK * C_EMBD];   // x   as tf32  64 MB
__device__ __align__(16) uint32_t g_wa[F_QKV * C_EMBD];   // w_attn tf32  12 MB
__device__ __align__(16) uint32_t g_wp[C_EMBD * C_EMBD];  // w_proj tf32   4 MB
__device__ __align__(16) uint32_t g_ya[M_TOK * C_EMBD];   // attn out tf32 64 MB
__device__ __align__(16) float    g_rc[CHUNK * 32];       // rope cos table
__device__ __align__(16) float    g_rs[CHUNK * 32];       // rope sin table

__device__ __forceinline__ uint32_t f2tf32(float x) {
    uint32_t r;
    asm("cvt.rna.tf32.f32 %0, %1;" : "=r"(r) : "f"(x));
    return r;
}
__device__ __forceinline__ uint32_t smem_u32(const void* p) {
    uint32_t a;
    asm("{ .reg .u64 t; cvta.to.shared.u64 t, %1; cvt.u32.u64 %0, t; }"
        : "=r"(a) : "l"(p));
    return a;
}
// m16n8k8 tf32 mma: D(16x8,f32) += A(16x8,row) * B(8x8,col)
__device__ __forceinline__ void mma_tf32(float* d, const uint32_t* a,
                                         uint32_t b0, uint32_t b1) {
    asm volatile(
        "mma.sync.aligned.m16n8k8.row.col.f32.tf32.tf32.f32 "
        "{%0,%1,%2,%3}, {%4,%5,%6,%7}, {%8,%9}, {%0,%1,%2,%3};"
        : "+f"(d[0]), "+f"(d[1]), "+f"(d[2]), "+f"(d[3])
        : "r"(a[0]), "r"(a[1]), "r"(a[2]), "r"(a[3]), "r"(b0), "r"(b1));
}

// ============================================================================
// Elementwise fp32 -> tf32(rna) conversion (vectorized)
// ============================================================================
__global__ __launch_bounds__(256) void cvt_tf32(const float4* __restrict__ in,
                                                uint4* __restrict__ out, int n4) {
    int i = blockIdx.x * blockDim.x + threadIdx.x;
    if (i < n4) {
        float4 v = in[i];
        out[i] = make_uint4(f2tf32(v.x), f2tf32(v.y), f2tf32(v.z), f2tf32(v.w));
    }
}

// RoPE table init: cos/sin(s * 10000^(-i/32)), s in [0,64), i in [0,32)
__global__ void rope_init() {
    const int e = blockIdx.x * blockDim.x + threadIdx.x;  // 0..2047
    if (e < CHUNK * 32) {
        const int s = e >> 5;
        const int i = e & 31;
        const float invf = __expf(-((float)i * (1.0f / 32.0f)) * 9.210340371976184f);
        float sn, c;
        sincosf((float)s * invf, &sn, &c);
        g_rc[e] = c;
        g_rs[e] = sn;
    }
}

// ============================================================================
// NT GEMM via mma.sync tf32, pre-converted inputs, cp.async 3-stage pipeline.
// C[m,n] = sum_k A[m,k]*B[n,k];  A:[M,K] u32, B:[N,K] u32, C fp32.
// CTA tile 128x256, BK=32; 512 threads = 16 warps (2m x 8n), warp tile 64x32.
// Requires M%128==0, N%256==0, K%32==0.
// ============================================================================
#define BM 128
#define BN 256
#define PADK 36
#define A_STG (BM * PADK)               // 4608 u32
#define B_STG (BN * PADK)               // 9216 u32
#define STG_U (A_STG + B_STG)           // 13824 u32 = 55296 B
#define STAGES 3
#define G_SMEM_BYTES (STAGES * STG_U * 4)   // 162 KB

__global__ __launch_bounds__(512, 1) void gemm_mma(const uint32_t* __restrict__ A,
                                                   const uint32_t* __restrict__ B,
                                                   float* __restrict__ C,
                                                   int N, int K) {
    extern __shared__ uint32_t smu[];
    const uint32_t sbase = smem_u32(smu);
    const int tid = threadIdx.x;
    const int lane = tid & 31;
    const int wid = tid >> 5;            // 0..15
    const int warp_m = wid & 1;          // 0..1 -> 64 rows
    const int warp_n = wid >> 1;         // 0..7 -> 32 cols
    const int bx = blockIdx.x;
    const int by = blockIdx.y;
    const int r0 = lane >> 2;            // 0..7
    const int c0 = lane & 3;             // 0..3

    const uint32_t* Agp = A + (size_t)(by * BM) * K;
    const uint32_t* Bgp = B + (size_t)(bx * BN) * K;

    // Issue async copy of K-chunk c into stage s (A: 2 segs/thread, B: 4)
    auto issue_copy = [&](int c, int s) {
        const uint32_t so = (uint32_t)(s * STG_U) * 4;
        const uint32_t koff = (uint32_t)c * 32;
#pragma unroll
        for (int i = 0; i < 2; i++) {
            const int seg = tid + i * 512;          // 0..1023
            const int row = seg >> 3, sg = seg & 7;
            const uint32_t dst = sbase + so + (uint32_t)(row * PADK + sg * 4) * 4;
            const uint32_t* src = Agp + (size_t)row * K + koff + sg * 4;
            asm volatile("cp.async.cg.shared.global [%0], [%1], 16;"
                         :: "r"(dst), "l"(src));
        }
#pragma unroll
        for (int i = 0; i < 4; i++) {
            const int seg = tid + i * 512;          // 0..2047
            const int row = seg >> 3, sg = seg & 7;
            const uint32_t dst =
                sbase + so + (uint32_t)(A_STG + row * PADK + sg * 4) * 4;
            const uint32_t* src = Bgp + (size_t)row * K + koff + sg * 4;
            asm volatile("cp.async.cg.shared.global [%0], [%1], 16;"
                         :: "r"(dst), "l"(src));
        }
        asm volatile("cp.async.commit_group;");
    };

    float acc[4][4][4];
#pragma unroll
    for (int mf = 0; mf < 4; mf++)
#pragma unroll
        for (int nf = 0; nf < 4; nf++)
#pragma unroll
            for (int e = 0; e < 4; e++) acc[mf][nf][e] = 0.0f;

    const int nch = K >> 5;
    issue_copy(0, 0);
    issue_copy(1, 1);

    for (int c = 0; c < nch; c++) {
        const int s = c % STAGES;
        if (c + 2 < nch) {
            asm volatile("cp.async.wait_group 1;" ::: "memory");
        } else {
            asm volatile("cp.async.wait_group 0;" ::: "memory");
        }
        __syncthreads();   // chunk c visible; all warps done reading stage (c-1)%3
        if (c + 2 < nch) issue_copy(c + 2, (c + 2) % STAGES);

        const uint32_t* As = smu + s * STG_U;
        const uint32_t* Bs = As + A_STG;

#pragma unroll
        for (int ks = 0; ks < 4; ks++) {
            const int k0 = ks * 8;
            uint32_t af[4][4];
#pragma unroll
            for (int mf = 0; mf < 4; mf++) {
                const int base = (warp_m * 64 + mf * 16 + r0) * PADK + k0 + c0;
                af[mf][0] = As[base];
                af[mf][1] = As[base + 8 * PADK];
                af[mf][2] = As[base + 4];
                af[mf][3] = As[base + 8 * PADK + 4];
            }
#pragma unroll
            for (int nf = 0; nf < 4; nf++) {
                const int base = (warp_n * 32 + nf * 8 + r0) * PADK + k0 + c0;
                const uint32_t b0 = Bs[base];
                const uint32_t b1 = Bs[base + 4];
#pragma unroll
                for (int mf = 0; mf < 4; mf++)
                    mma_tf32(acc[mf][nf], af[mf], b0, b1);
            }
        }
    }

    // Epilogue: c{0,1} at (row, 2c0), c{2,3} at (row+8, 2c0)
    const int mrow = by * BM + warp_m * 64 + r0;
    const int ncol = bx * BN + warp_n * 32 + c0 * 2;
#pragma unroll
    for (int mf = 0; mf < 4; mf++) {
#pragma unroll
        for (int nf = 0; nf < 4; nf++) {
            float* p0 = C + (size_t)(mrow + mf * 16) * N + ncol + nf * 8;
            float* p1 = p0 + 8 * N;
            *(float2*)p0 = make_float2(acc[mf][nf][0], acc[mf][nf][1]);
            *(float2*)p1 = make_float2(acc[mf][nf][2], acc[mf][nf][3]);
        }
    }
}

// ----------------------------------------------------------------------------
// Chunked attention: one CTA per (batch, chunk, head). Full fp32 math,
// RoPE via precomputed tables, output written directly as tf32(rna) u32.
// ----------------------------------------------------------------------------
#define ATT_PAD 68
#define ATT_SMEM_BYTES (4 * 64 * ATT_PAD * 4)

__global__ __launch_bounds__(256) void attn_kernel() {
    extern __shared__ float sm[];
    float* qs = sm;                        // 64 x 68
    float* ks = qs + 64 * ATT_PAD;
    float* vs = ks + 64 * ATT_PAD;
    float* ss = vs + 64 * ATT_PAD;         // scores / probs

    const int tid = threadIdx.x;
    const int bid = blockIdx.x;            // 0 .. 4095
    const int h = bid & 15;
    const int n = (bid >> 4) & 63;
    const int b = bid >> 10;

    const int tokbase = b * SEQ + n * CHUNK;

    // Load q,k with RoPE (table lookup): out[i]=x1*c+x2*s; out[i+32]=-x1*s+x2*c
    for (int e = tid; e < 64 * 32; e += 256) {
        const int s = e >> 5;
        const int i = e & 31;
        const float c = g_rc[e];
        const float sn = g_rs[e];
        const size_t base = (size_t)(tokbase + s) * F_QKV + h * HEAD_D;
        const float q1 = g_qkv[base + i];
        const float q2 = g_qkv[base + 32 + i];
        qs[s * ATT_PAD + i]      =  q1 * c + q2 * sn;
        qs[s * ATT_PAD + 32 + i] = -q1 * sn + q2 * c;
        const float k1 = g_qkv[base + C_EMBD + i];
        const float k2 = g_qkv[base + C_EMBD + 32 + i];
        ks[s * ATT_PAD + i]      =  k1 * c + k2 * sn;
        ks[s * ATT_PAD + 32 + i] = -k1 * sn + k2 * c;
    }
    for (int e = tid; e < 64 * 64; e += 256) {
        const int s = e >> 6;
        const int dd = e & 63;
        vs[s * ATT_PAD + dd] =
            g_qkv[(size_t)(tokbase + s) * F_QKV + 2 * C_EMBD + h * HEAD_D + dd];
    }
    __syncthreads();

    {
        const int qrt = (tid >> 4) << 2;
        const int kct = (tid & 15) << 2;
        float acc[4][4];
#pragma unroll
        for (int r = 0; r < 4; r++)
#pragma unroll
            for (int c = 0; c < 4; c++) acc[r][c] = 0.0f;

        for (int i = 0; i < 64; i += 4) {
            float4 qv[4], kv[4];
#pragma unroll
            for (int r = 0; r < 4; r++)
                qv[r] = *(const float4*)&qs[(qrt + r) * ATT_PAD + i];
#pragma unroll
            for (int c = 0; c < 4; c++)
                kv[c] = *(const float4*)&ks[(kct + c) * ATT_PAD + i];
#pragma unroll
            for (int r = 0; r < 4; r++)
#pragma unroll
                for (int c = 0; c < 4; c++)
                    acc[r][c] += qv[r].x * kv[c].x + qv[r].y * kv[c].y +
                                 qv[r].z * kv[c].z + qv[r].w * kv[c].w;
        }
        const float scale = 0.125f;
#pragma unroll
        for (int r = 0; r < 4; r++)
            *(float4*)&ss[(qrt + r) * ATT_PAD + kct] =
                make_float4(acc[r][0] * scale, acc[r][1] * scale,
                            acc[r][2] * scale, acc[r][3] * scale);
    }
    __syncthreads();

    {
        const int row = tid >> 2;
        const int g = tid & 3;
        float loc[16];
        float m = -1e30f;
#pragma unroll
        for (int j = 0; j < 16; j++) {
            loc[j] = ss[row * ATT_PAD + g * 16 + j];
            m = fmaxf(m, loc[j]);
        }
        m = fmaxf(m, __shfl_xor_sync(0xffffffffu, m, 1));
        m = fmaxf(m, __shfl_xor_sync(0xffffffffu, m, 2));
        float sum = 0.0f;
#pragma unroll
        for (int j = 0; j < 16; j++) {
            loc[j] = __expf(loc[j] - m);
            sum += loc[j];
        }
        sum += __shfl_xor_sync(0xffffffffu, sum, 1);
        sum += __shfl_xor_sync(0xffffffffu, sum, 2);
        const float inv = 1.0f / sum;
#pragma unroll
        for (int j = 0; j < 16; j++)
            ss[row * ATT_PAD + g * 16 + j] = loc[j] * inv;
    }
    __syncthreads();

    {
        const int qrt = (tid >> 4) << 2;
        const int ddt = (tid & 15) << 2;
        float acc[4][4];
#pragma unroll
        for (int r = 0; r < 4; r++)
#pragma unroll
            for (int c = 0; c < 4; c++) acc[r][c] = 0.0f;

        for (int kc = 0; kc < 64; kc += 4) {
            float4 pv[4], vv[4];
#pragma unroll
            for (int r = 0; r < 4; r++)
                pv[r] = *(const float4*)&ss[(qrt + r) * ATT_PAD + kc];
#pragma unroll
            for (int m2 = 0; m2 < 4; m2++)
                vv[m2] = *(const float4*)&vs[(kc + m2) * ATT_PAD + ddt];
#pragma unroll
            for (int r = 0; r < 4; r++) {
                acc[r][0] += pv[r].x * vv[0].x + pv[r].y * vv[1].x +
                             pv[r].z * vv[2].x + pv[r].w * vv[3].x;
                acc[r][1] += pv[r].x * vv[0].y + pv[r].y * vv[1].y +
                             pv[r].z * vv[2].y + pv[r].w * vv[3].y;
                acc[r][2] += pv[r].x * vv[0].z + pv[r].y * vv[1].z +
                             pv[r].z * vv[2].z + pv[r].w * vv[3].z;
                acc[r][3] += pv[r].x * vv[0].w + pv[r].y * vv[1].w +
                             pv[r].z * vv[2].w + pv[r].w * vv[3].w;
            }
        }
#pragma unroll
        for (int r = 0; r < 4; r++)
            *(uint4*)&g_ya[(size_t)(tokbase + qrt + r) * C_EMBD + h * HEAD_D + ddt] =
                make_uint4(f2tf32(acc[r][0]), f2tf32(acc[r][1]),
                           f2tf32(acc[r][2]), f2tf32(acc[r][3]));
    }
}

// ----------------------------------------------------------------------------
extern "C" void kernel_launch(void* const* d_in, const int* in_sizes, int n_in,
                              void* d_out, int out_size) {
    const float* x      = (const float*)d_in[0];   // [4,4096,1024]
    const float* w_attn = (const float*)d_in[1];   // [3072,1024]
    const float* w_proj = (const float*)d_in[2];   // [1024,1024]
    float* out = (float*)d_out;                    // [4,4096,1024]

    float*    qkv = nullptr;
    uint32_t *xa = nullptr, *wa = nullptr, *wp = nullptr, *ya = nullptr;
    cudaGetSymbolAddress((void**)&qkv, g_qkv);
    cudaGetSymbolAddress((void**)&xa, g_xa);
    cudaGetSymbolAddress((void**)&wa, g_wa);
    cudaGetSymbolAddress((void**)&wp, g_wp);
    cudaGetSymbolAddress((void**)&ya, g_ya);

    cudaFuncSetAttribute(gemm_mma,
                         cudaFuncAttributeMaxDynamicSharedMemorySize,
                         G_SMEM_BYTES);
    cudaFuncSetAttribute(attn_kernel,
                         cudaFuncAttributeMaxDynamicSharedMemorySize,
                         ATT_SMEM_BYTES);

    dim3 blk(256);
    // fp32 -> tf32 pre-conversion + rope tables
    const int n4x = M_TOK * C_EMBD / 4;
    const int n4a = F_QKV * C_EMBD / 4;
    const int n4p = C_EMBD * C_EMBD / 4;
    cvt_tf32<<<(n4x + 255) / 256, blk>>>((const float4*)x, (uint4*)xa, n4x);
    cvt_tf32<<<(n4a + 255) / 256, blk>>>((const float4*)w_attn, (uint4*)wa, n4a);
    cvt_tf32<<<(n4p + 255) / 256, blk>>>((const float4*)w_proj, (uint4*)wp, n4p);
    rope_init<<<8, 256>>>();

    // qkv = x @ w_attn^T
    gemm_mma<<<dim3(F_QKV / BN, M_TOK / BM), dim3(512), G_SMEM_BYTES>>>(
        xa, wa, qkv, F_QKV, C_EMBD);
    // per-chunk attention (RoPE fused), writes tf32 y
    attn_kernel<<<BATCH * (SEQ / CHUNK) * N_HEAD, blk, ATT_SMEM_BYTES>>>();
    // out = y @ w_proj^T
    gemm_mma<<<dim3(C_EMBD / BN, M_TOK / BM), dim3(512), G_SMEM_BYTES>>>(
        ya, wp, out, C_EMBD, C_EMBD);
}